// round 1
// baseline (speedup 1.0000x reference)
#include <cuda_runtime.h>
#include <cstdint>

// Problem constants
#define BATCH   2
#define SEQ     2048
#define DMODEL  2048
#define NHEADS  16
#define DHEAD   128

// ---------------------------------------------------------------------------
// Scratch (alloc-free: __device__ globals)
// g_Q/g_K/g_V laid out [B*H, S, DHEAD]; g_O laid out [B, S, H, DHEAD] == [B,S,D]
// ---------------------------------------------------------------------------
__device__ float g_Q[(size_t)BATCH * NHEADS * SEQ * DHEAD];
__device__ float g_K[(size_t)BATCH * NHEADS * SEQ * DHEAD];
__device__ float g_V[(size_t)BATCH * NHEADS * SEQ * DHEAD];
__device__ float g_O[(size_t)BATCH * SEQ * DMODEL];

// ---------------------------------------------------------------------------
// NT GEMM: C[m,n] = sum_k A[m,k] * B[n,k]
// A: [M,K] row-major, B: [N,K] row-major.
// Tile 128x128xBK16, 256 threads, 8x8 per thread.
// MODE 0: plain write C row-major [M,N]
// MODE 1: QKV scatter into g_Q/g_K/g_V ([B*H, S, DHEAD] layout); C unused
// ---------------------------------------------------------------------------
template <int MODE>
__global__ void __launch_bounds__(256)
gemm_nt(const float* __restrict__ A, const float* __restrict__ B,
        float* __restrict__ C, int M, int N, int K)
{
    __shared__ float As[16][128];
    __shared__ float Bs[16][128];

    const int tid = threadIdx.x;
    const int tx  = tid & 15;        // 0..15 -> 8 output cols each
    const int ty  = tid >> 4;        // 0..15 -> 8 output rows each
    const int m0  = blockIdx.y * 128;
    const int n0  = blockIdx.x * 128;
    const int lr  = tid >> 2;        // load row 0..63 (+64 second iter)
    const int lc  = tid & 3;         // load float4 col 0..3 (BK=16)

    float acc[8][8];
#pragma unroll
    for (int i = 0; i < 8; i++)
#pragma unroll
        for (int j = 0; j < 8; j++) acc[i][j] = 0.0f;

    const float* Ab = A + (size_t)m0 * K;
    const float* Bb = B + (size_t)n0 * K;

    for (int k0 = 0; k0 < K; k0 += 16) {
#pragma unroll
        for (int it = 0; it < 2; it++) {
            int row = lr + it * 64;
            float4 a = *(const float4*)(Ab + (size_t)row * K + k0 + lc * 4);
            As[lc * 4 + 0][row] = a.x;
            As[lc * 4 + 1][row] = a.y;
            As[lc * 4 + 2][row] = a.z;
            As[lc * 4 + 3][row] = a.w;
            float4 b = *(const float4*)(Bb + (size_t)row * K + k0 + lc * 4);
            Bs[lc * 4 + 0][row] = b.x;
            Bs[lc * 4 + 1][row] = b.y;
            Bs[lc * 4 + 2][row] = b.z;
            Bs[lc * 4 + 3][row] = b.w;
        }
        __syncthreads();

#pragma unroll
        for (int kk = 0; kk < 16; kk++) {
            float ra[8], rb[8];
            *(float4*)&ra[0] = *(const float4*)&As[kk][ty * 8];
            *(float4*)&ra[4] = *(const float4*)&As[kk][ty * 8 + 4];
            *(float4*)&rb[0] = *(const float4*)&Bs[kk][tx * 8];
            *(float4*)&rb[4] = *(const float4*)&Bs[kk][tx * 8 + 4];
#pragma unroll
            for (int i = 0; i < 8; i++)
#pragma unroll
                for (int j = 0; j < 8; j++)
                    acc[i][j] += ra[i] * rb[j];
        }
        __syncthreads();
    }

    if (MODE == 0) {
#pragma unroll
        for (int i = 0; i < 8; i++) {
            float* cp = C + (size_t)(m0 + ty * 8 + i) * N + n0 + tx * 8;
            *(float4*)cp       = make_float4(acc[i][0], acc[i][1], acc[i][2], acc[i][3]);
            *(float4*)(cp + 4) = make_float4(acc[i][4], acc[i][5], acc[i][6], acc[i][7]);
        }
    } else {
        // n0 is a multiple of 128 => this block covers exactly one (t, h) slab
        const int t = n0 >> 11;               // 0=Q, 1=K, 2=V
        const int h = (n0 >> 7) & (NHEADS - 1);
        const int b = m0 >> 11;               // m0 multiple of 128, batch at 2048
        const int s0 = (m0 & (SEQ - 1)) + ty * 8;
        float* dst = (t == 0 ? g_Q : (t == 1 ? g_K : g_V)) +
                     (size_t)(b * NHEADS + h) * SEQ * DHEAD;
#pragma unroll
        for (int i = 0; i < 8; i++) {
            float* cp = dst + (size_t)(s0 + i) * DHEAD + tx * 8;
            *(float4*)cp       = make_float4(acc[i][0], acc[i][1], acc[i][2], acc[i][3]);
            *(float4*)(cp + 4) = make_float4(acc[i][4], acc[i][5], acc[i][6], acc[i][7]);
        }
    }
}

// ---------------------------------------------------------------------------
// Flash attention (fp32, causal). grid = (SEQ/64, B*H), 256 threads.
// Br = Bc = 64. Online softmax. Writes g_O in [B, S, H, DHEAD] layout.
// ---------------------------------------------------------------------------
#define BR 64
#define BC 64
#define SQ_STRIDE 129
#define SK_STRIDE 129
#define SV_STRIDE 132
#define SP_STRIDE 68
#define ATT_SMEM_FLOATS (BR * SQ_STRIDE + BC * SK_STRIDE + BC * SV_STRIDE + BR * SP_STRIDE + 2 * BR)
#define ATT_SMEM_BYTES  (ATT_SMEM_FLOATS * 4)

__global__ void __launch_bounds__(256)
flash_attn_kernel()
{
    extern __shared__ float smem[];
    float* sQ = smem;                          // [BR][SQ_STRIDE]
    float* sK = sQ + BR * SQ_STRIDE;           // [BC][SK_STRIDE]
    float* sV = sK + BC * SK_STRIDE;           // [BC][SV_STRIDE]
    float* sP = sV + BC * SV_STRIDE;           // [BR][SP_STRIDE]
    float* sm = sP + BR * SP_STRIDE;           // [BR] running max
    float* sl = sm + BR;                       // [BR] running sum

    const int tid = threadIdx.x;
    const int qb  = blockIdx.x;
    const int bh  = blockIdx.y;
    const int q0  = qb * BR;
    const int b   = bh >> 4;
    const int h   = bh & (NHEADS - 1);

    const float* Qb = g_Q + (size_t)bh * SEQ * DHEAD;
    const float* Kb = g_K + (size_t)bh * SEQ * DHEAD;
    const float* Vb = g_V + (size_t)bh * SEQ * DHEAD;

    // Load Q tile [BR][DHEAD] -> sQ (row-major, stride SQ_STRIDE)
#pragma unroll
    for (int it = 0; it < 8; it++) {
        int idx = tid + it * 256;              // 2048 float4s total
        int row = idx >> 5;
        int c4  = idx & 31;
        float4 v = *(const float4*)(Qb + (size_t)(q0 + row) * DHEAD + c4 * 4);
        float* p = sQ + row * SQ_STRIDE + c4 * 4;
        p[0] = v.x; p[1] = v.y; p[2] = v.z; p[3] = v.w;
    }
    if (tid < BR) { sm[tid] = -1e30f; sl[tid] = 0.0f; }

    const int ty = tid >> 4;                   // 0..15
    const int tx = tid & 15;                   // 0..15
    const int r0 = ty * 4;                     // 4 score/O rows per thread
    const int c0 = tx * 4;                     // 4 score cols per thread
    const int d0 = tx * 8;                     // 8 O cols per thread

    float o[4][8];
#pragma unroll
    for (int i = 0; i < 4; i++)
#pragma unroll
        for (int d = 0; d < 8; d++) o[i][d] = 0.0f;

    __syncthreads();

    const float scale = 0.08838834764831845f;  // 1/sqrt(128)

    for (int kb = 0; kb <= qb; kb++) {
        const int k0t = kb * BC;
        // Load K and V tiles
#pragma unroll
        for (int it = 0; it < 8; it++) {
            int idx = tid + it * 256;
            int row = idx >> 5;
            int c4  = idx & 31;
            float4 kv = *(const float4*)(Kb + (size_t)(k0t + row) * DHEAD + c4 * 4);
            float* kp = sK + row * SK_STRIDE + c4 * 4;
            kp[0] = kv.x; kp[1] = kv.y; kp[2] = kv.z; kp[3] = kv.w;
            float4 vv = *(const float4*)(Vb + (size_t)(k0t + row) * DHEAD + c4 * 4);
            float* vp = sV + row * SV_STRIDE + c4 * 4;
            vp[0] = vv.x; vp[1] = vv.y; vp[2] = vv.z; vp[3] = vv.w;
        }
        __syncthreads();

        // ---- scores: acc[4][4] = Q(r0..r0+3) . K(c0..c0+3)^T ----
        float acc[4][4];
#pragma unroll
        for (int i = 0; i < 4; i++)
#pragma unroll
            for (int j = 0; j < 4; j++) acc[i][j] = 0.0f;

#pragma unroll 4
        for (int k = 0; k < DHEAD; k++) {
            float qv[4], kv[4];
#pragma unroll
            for (int i = 0; i < 4; i++) qv[i] = sQ[(r0 + i) * SQ_STRIDE + k];
#pragma unroll
            for (int j = 0; j < 4; j++) kv[j] = sK[(c0 + j) * SK_STRIDE + k];
#pragma unroll
            for (int i = 0; i < 4; i++)
#pragma unroll
                for (int j = 0; j < 4; j++)
                    acc[i][j] += qv[i] * kv[j];
        }

        // ---- online softmax (per row; 16 lanes per row, same half-warp) ----
        float f[4];
#pragma unroll
        for (int i = 0; i < 4; i++) {
            const int qrow = q0 + r0 + i;
            float mloc = -1e30f;
#pragma unroll
            for (int j = 0; j < 4; j++) {
                float s = acc[i][j] * scale;
                if (k0t + c0 + j > qrow) s = -1e30f;
                acc[i][j] = s;
                mloc = fmaxf(mloc, s);
            }
#pragma unroll
            for (int off = 8; off >= 1; off >>= 1)
                mloc = fmaxf(mloc, __shfl_xor_sync(0xffffffffu, mloc, off));

            const float mold = sm[r0 + i];
            const float mnew = fmaxf(mold, mloc);
            f[i] = __expf(mold - mnew);

            float rs = 0.0f;
#pragma unroll
            for (int j = 0; j < 4; j++) {
                float p = __expf(acc[i][j] - mnew);
                acc[i][j] = p;
                rs += p;
            }
#pragma unroll
            for (int off = 8; off >= 1; off >>= 1)
                rs += __shfl_xor_sync(0xffffffffu, rs, off);

            if (tx == 0) {
                sm[r0 + i] = mnew;
                sl[r0 + i] = sl[r0 + i] * f[i] + rs;
            }
            *(float4*)&sP[(r0 + i) * SP_STRIDE + c0] =
                make_float4(acc[i][0], acc[i][1], acc[i][2], acc[i][3]);
        }
        __syncthreads();

        // ---- rescale O then accumulate P @ V ----
#pragma unroll
        for (int i = 0; i < 4; i++)
#pragma unroll
            for (int d = 0; d < 8; d++) o[i][d] *= f[i];

#pragma unroll 2
        for (int c = 0; c < BC; c++) {
            float pv[4];
#pragma unroll
            for (int i = 0; i < 4; i++) pv[i] = sP[(r0 + i) * SP_STRIDE + c];
            float4 v1 = *(const float4*)&sV[c * SV_STRIDE + d0];
            float4 v2 = *(const float4*)&sV[c * SV_STRIDE + d0 + 4];
#pragma unroll
            for (int i = 0; i < 4; i++) {
                o[i][0] += pv[i] * v1.x;
                o[i][1] += pv[i] * v1.y;
                o[i][2] += pv[i] * v1.z;
                o[i][3] += pv[i] * v1.w;
                o[i][4] += pv[i] * v2.x;
                o[i][5] += pv[i] * v2.y;
                o[i][6] += pv[i] * v2.z;
                o[i][7] += pv[i] * v2.w;
            }
        }
        __syncthreads();
    }

    // ---- epilogue: divide by l, write [B, S, H, DHEAD] ----
#pragma unroll
    for (int i = 0; i < 4; i++) {
        const float inv = 1.0f / sl[r0 + i];
        const int srow = q0 + r0 + i;
        float* op = g_O + (((size_t)b * SEQ + srow) * NHEADS + h) * DHEAD + d0;
        *(float4*)op       = make_float4(o[i][0] * inv, o[i][1] * inv, o[i][2] * inv, o[i][3] * inv);
        *(float4*)(op + 4) = make_float4(o[i][4] * inv, o[i][5] * inv, o[i][6] * inv, o[i][7] * inv);
    }
}

// ---------------------------------------------------------------------------
// Launch: qkv GEMM -> flash attention -> output GEMM
// Inputs: d_in[0]=x [B,S,D] f32, d_in[1]=W_qkv [3D,D] f32,
//         d_in[2]=W_out [D,D] f32, d_in[3]=mask (unused, causal known)
// ---------------------------------------------------------------------------
extern "C" void kernel_launch(void* const* d_in, const int* in_sizes, int n_in,
                              void* d_out, int out_size)
{
    const float* x    = (const float*)d_in[0];
    const float* Wqkv = (const float*)d_in[1];
    const float* Wout = (const float*)d_in[2];
    float* out = (float*)d_out;

    const int M = BATCH * SEQ;          // 4096

    // Stage 1: QKV projection (scatter epilogue into g_Q/g_K/g_V)
    gemm_nt<1><<<dim3((3 * DMODEL) / 128, M / 128), 256>>>(
        x, Wqkv, nullptr, M, 3 * DMODEL, DMODEL);

    // Stage 2: flash attention
    cudaFuncSetAttribute(flash_attn_kernel,
                         cudaFuncAttributeMaxDynamicSharedMemorySize,
                         ATT_SMEM_BYTES);
    flash_attn_kernel<<<dim3(SEQ / BR, BATCH * NHEADS), 256, ATT_SMEM_BYTES>>>();

    // Stage 3: output projection from g_O
    float* oPtr = nullptr;
    cudaGetSymbolAddress((void**)&oPtr, g_O);
    gemm_nt<0><<<dim3(DMODEL / 128, M / 128), 256>>>(
        oPtr, Wout, out, M, DMODEL, DMODEL);
}

// round 3
// speedup vs baseline: 2.0752x; 2.0752x over previous
#include <cuda_runtime.h>
#include <cstdint>

// Problem constants
#define BATCH   2
#define SEQ     2048
#define DMODEL  2048
#define NHEADS  16
#define DHEAD   128

// ---------------------------------------------------------------------------
// Scratch (alloc-free: __device__ globals)
// ---------------------------------------------------------------------------
__device__ float g_Q[(size_t)BATCH * NHEADS * SEQ * DHEAD];
__device__ float g_K[(size_t)BATCH * NHEADS * SEQ * DHEAD];
__device__ float g_V[(size_t)BATCH * NHEADS * SEQ * DHEAD];
__device__ float g_O[(size_t)BATCH * SEQ * DMODEL];

__device__ __forceinline__ uint32_t f2tf(float x) {
    uint32_t r;
    asm("cvt.rna.tf32.f32 %0, %1;" : "=r"(r) : "f"(x));
    return r;
}

__device__ __forceinline__ void mma_tf32(float* d, const uint32_t* a, const uint32_t* b) {
    asm volatile(
        "mma.sync.aligned.m16n8k8.row.col.f32.tf32.tf32.f32 "
        "{%0,%1,%2,%3}, {%4,%5,%6,%7}, {%8,%9}, {%0,%1,%2,%3};"
        : "+f"(d[0]), "+f"(d[1]), "+f"(d[2]), "+f"(d[3])
        : "r"(a[0]), "r"(a[1]), "r"(a[2]), "r"(a[3]), "r"(b[0]), "r"(b[1]));
}

// ---------------------------------------------------------------------------
// tf32 mma.sync NT GEMM: C[m,n] = sum_k A[m,k] * B[n,k], K = DMODEL = 2048
// Block tile 128x128, K-chunk 32, 8 warps (2x4), warp tile 64x32 (4x4 mma).
// Smem holds fragments directly (per-lane a0..a3 / b0..b1 contiguous):
//   A frag block (gm*4+ks) in [0,32): stride 33 lanes of 16B
//   B frag block (gn*4+ks) in [0,64): stride 33 lanes of 8B
// MODE 0: write C row-major [M,N].  MODE 1: QKV scatter into g_Q/g_K/g_V.
// ---------------------------------------------------------------------------
#define KC  32
#define NCH (DMODEL / KC)                  // 64
#define AFRAG_BYTES (32 * 33 * 16)         // 16896
#define BFRAG_BYTES (64 * 33 * 8)          // 16896
#define BUFBYTES (AFRAG_BYTES + BFRAG_BYTES)
#define GEMM_SMEM (2 * BUFBYTES)           // 67584

template <int MODE>
__global__ void __launch_bounds__(256)
gemm_mma(const float* __restrict__ A, const float* __restrict__ B,
         float* __restrict__ C, int N)
{
    extern __shared__ char smemc[];
    const int tid = threadIdx.x;
    const int wid = tid >> 5;
    const int lid = tid & 31;
    const int wm  = wid & 1;               // 0..1 : 64-row slab
    const int wn  = wid >> 1;              // 0..3 : 32-col slab
    const int m0  = blockIdx.y * 128;
    const int n0  = blockIdx.x * 128;

    float acc[4][4][4];
#pragma unroll
    for (int i = 0; i < 4; i++)
#pragma unroll
        for (int j = 0; j < 4; j++)
#pragma unroll
            for (int v = 0; v < 4; v++) acc[i][j][v] = 0.0f;

    const float* Ab = A + (size_t)m0 * DMODEL;
    const float* Bb = B + (size_t)n0 * DMODEL;

    float4 ar[4], br[4];

    // ---- gmem load of one chunk into registers ----
    auto ldg_chunk = [&](int k0) {
#pragma unroll
        for (int it = 0; it < 4; it++) {
            const int idx = tid + it * 256;
            const int row = idx >> 3;
            const int c4  = idx & 7;
            ar[it] = *(const float4*)(Ab + (size_t)row * DMODEL + k0 + c4 * 4);
            br[it] = *(const float4*)(Bb + (size_t)row * DMODEL + k0 + c4 * 4);
        }
    };

    // ---- regs -> smem fragment layout (with tf32 rounding) ----
    auto sts_chunk = [&](int buf) {
        char* bp = smemc + buf * BUFBYTES;
#pragma unroll
        for (int it = 0; it < 4; it++) {
            const int idx = tid + it * 256;
            const int row = idx >> 3;
            const int c4  = idx & 7;
            const int ks  = c4 >> 1;
            // A: frag block (gm*4+ks), lane = r*4+j, slot = (khalf<<1)|mhalf
            {
                const int gm   = row >> 4;
                const int r    = row & 7;
                const int slot = ((c4 & 1) << 1) | ((row >> 3) & 1);
                uint32_t* p = (uint32_t*)(bp + ((gm * 4 + ks) * 33 + r * 4) * 16 + slot * 4);
                p[0]  = f2tf(ar[it].x);
                p[4]  = f2tf(ar[it].y);
                p[8]  = f2tf(ar[it].z);
                p[12] = f2tf(ar[it].w);
            }
            // B: frag block (gn*4+ks), lane = n*4+j, slot = khalf
            {
                const int gn  = row >> 3;
                const int nl  = (row & 7) * 4;
                const int slb = c4 & 1;
                uint32_t* q = (uint32_t*)(bp + AFRAG_BYTES + ((gn * 4 + ks) * 33 + nl) * 8 + slb * 4);
                q[0] = f2tf(br[it].x);
                q[2] = f2tf(br[it].y);
                q[4] = f2tf(br[it].z);
                q[6] = f2tf(br[it].w);
            }
        }
    };

    // prologue
    ldg_chunk(0);
    sts_chunk(0);
    __syncthreads();

    for (int c = 0; c < NCH; ++c) {
        const int buf = c & 1;
        if (c + 1 < NCH) ldg_chunk((c + 1) * KC);

        const uint32_t* fA = (const uint32_t*)(smemc + buf * BUFBYTES);
        const uint32_t* fB = (const uint32_t*)(smemc + buf * BUFBYTES + AFRAG_BYTES);
#pragma unroll
        for (int ks = 0; ks < 4; ks++) {
            uint32_t a[4][4], b[4][2];
#pragma unroll
            for (int mt = 0; mt < 4; mt++)
                *(uint4*)a[mt] = *(const uint4*)&fA[(((wm * 4 + mt) * 4 + ks) * 33 + lid) * 4];
#pragma unroll
            for (int nt = 0; nt < 4; nt++)
                *(uint2*)b[nt] = *(const uint2*)&fB[(((wn * 4 + nt) * 4 + ks) * 33 + lid) * 2];
#pragma unroll
            for (int mt = 0; mt < 4; mt++)
#pragma unroll
                for (int nt = 0; nt < 4; nt++)
                    mma_tf32(acc[mt][nt], a[mt], b[nt]);
        }

        if (c + 1 < NCH) sts_chunk(buf ^ 1);
        __syncthreads();
    }

    // ---- epilogue ----
    const int lr = lid >> 2;                // 0..7
    const int lc = (lid & 3) * 2;           // 0,2,4,6
#pragma unroll
    for (int mt = 0; mt < 4; mt++) {
        const int mrow = wm * 64 + mt * 16 + lr;
#pragma unroll
        for (int nt = 0; nt < 4; nt++) {
            const int ncol = wn * 32 + nt * 8 + lc;
            if (MODE == 0) {
                float* dst = C + (size_t)(m0 + mrow) * N + n0 + ncol;
                *(float2*)dst                    = make_float2(acc[mt][nt][0], acc[mt][nt][1]);
                *(float2*)(dst + (size_t)8 * N)  = make_float2(acc[mt][nt][2], acc[mt][nt][3]);
            } else {
                const int t = n0 >> 11;                      // 0=Q,1=K,2=V
                const int h = (n0 >> 7) & (NHEADS - 1);
                const int b = m0 >> 11;
                const int s = (m0 & (SEQ - 1)) + mrow;
                float* basep = (t == 0 ? g_Q : (t == 1 ? g_K : g_V));
                float* dst = basep + ((size_t)(b * NHEADS + h) * SEQ + s) * DHEAD + ncol;
                *(float2*)dst                 = make_float2(acc[mt][nt][0], acc[mt][nt][1]);
                *(float2*)(dst + 8 * DHEAD)   = make_float2(acc[mt][nt][2], acc[mt][nt][3]);
            }
        }
    }
}

// ---------------------------------------------------------------------------
// Flash attention (fp32, causal). grid = (SEQ/64, B*H), 256 threads.
// ---------------------------------------------------------------------------
#define BR 64
#define BC 64
#define SQ_STRIDE 129
#define SK_STRIDE 129
#define SV_STRIDE 132
#define SP_STRIDE 68
#define ATT_SMEM_FLOATS (BR * SQ_STRIDE + BC * SK_STRIDE + BC * SV_STRIDE + BR * SP_STRIDE + 2 * BR)
#define ATT_SMEM_BYTES  (ATT_SMEM_FLOATS * 4)

__global__ void __launch_bounds__(256)
flash_attn_kernel()
{
    extern __shared__ float smem[];
    float* sQ = smem;
    float* sK = sQ + BR * SQ_STRIDE;
    float* sV = sK + BC * SK_STRIDE;
    float* sP = sV + BC * SV_STRIDE;
    float* smx = sP + BR * SP_STRIDE;
    float* sl = smx + BR;

    const int tid = threadIdx.x;
    const int qb  = blockIdx.x;
    const int bh  = blockIdx.y;
    const int q0  = qb * BR;
    const int b   = bh >> 4;
    const int h   = bh & (NHEADS - 1);

    const float* Qb = g_Q + (size_t)bh * SEQ * DHEAD;
    const float* Kb = g_K + (size_t)bh * SEQ * DHEAD;
    const float* Vb = g_V + (size_t)bh * SEQ * DHEAD;

#pragma unroll
    for (int it = 0; it < 8; it++) {
        int idx = tid + it * 256;
        int row = idx >> 5;
        int c4  = idx & 31;
        float4 v = *(const float4*)(Qb + (size_t)(q0 + row) * DHEAD + c4 * 4);
        float* p = sQ + row * SQ_STRIDE + c4 * 4;
        p[0] = v.x; p[1] = v.y; p[2] = v.z; p[3] = v.w;
    }
    if (tid < BR) { smx[tid] = -1e30f; sl[tid] = 0.0f; }

    const int ty = tid >> 4;
    const int tx = tid & 15;
    const int r0 = ty * 4;
    const int c0 = tx * 4;
    const int d0 = tx * 8;

    float o[4][8];
#pragma unroll
    for (int i = 0; i < 4; i++)
#pragma unroll
        for (int d = 0; d < 8; d++) o[i][d] = 0.0f;

    __syncthreads();

    const float scale = 0.08838834764831845f;

    for (int kb = 0; kb <= qb; kb++) {
        const int k0t = kb * BC;
#pragma unroll
        for (int it = 0; it < 8; it++) {
            int idx = tid + it * 256;
            int row = idx >> 5;
            int c4  = idx & 31;
            float4 kv = *(const float4*)(Kb + (size_t)(k0t + row) * DHEAD + c4 * 4);
            float* kp = sK + row * SK_STRIDE + c4 * 4;
            kp[0] = kv.x; kp[1] = kv.y; kp[2] = kv.z; kp[3] = kv.w;
            float4 vv = *(const float4*)(Vb + (size_t)(k0t + row) * DHEAD + c4 * 4);
            float* vp = sV + row * SV_STRIDE + c4 * 4;
            vp[0] = vv.x; vp[1] = vv.y; vp[2] = vv.z; vp[3] = vv.w;
        }
        __syncthreads();

        float acc[4][4];
#pragma unroll
        for (int i = 0; i < 4; i++)
#pragma unroll
            for (int j = 0; j < 4; j++) acc[i][j] = 0.0f;

#pragma unroll 4
        for (int k = 0; k < DHEAD; k++) {
            float qv[4], kv[4];
#pragma unroll
            for (int i = 0; i < 4; i++) qv[i] = sQ[(r0 + i) * SQ_STRIDE + k];
#pragma unroll
            for (int j = 0; j < 4; j++) kv[j] = sK[(c0 + j) * SK_STRIDE + k];
#pragma unroll
            for (int i = 0; i < 4; i++)
#pragma unroll
                for (int j = 0; j < 4; j++)
                    acc[i][j] += qv[i] * kv[j];
        }

        float f[4];
#pragma unroll
        for (int i = 0; i < 4; i++) {
            const int qrow = q0 + r0 + i;
            float mloc = -1e30f;
#pragma unroll
            for (int j = 0; j < 4; j++) {
                float s = acc[i][j] * scale;
                if (k0t + c0 + j > qrow) s = -1e30f;
                acc[i][j] = s;
                mloc = fmaxf(mloc, s);
            }
#pragma unroll
            for (int off = 8; off >= 1; off >>= 1)
                mloc = fmaxf(mloc, __shfl_xor_sync(0xffffffffu, mloc, off));

            const float mold = smx[r0 + i];
            const float mnew = fmaxf(mold, mloc);
            f[i] = __expf(mold - mnew);

            float rs = 0.0f;
#pragma unroll
            for (int j = 0; j < 4; j++) {
                float p = __expf(acc[i][j] - mnew);
                acc[i][j] = p;
                rs += p;
            }
#pragma unroll
            for (int off = 8; off >= 1; off >>= 1)
                rs += __shfl_xor_sync(0xffffffffu, rs, off);

            if (tx == 0) {
                smx[r0 + i] = mnew;
                sl[r0 + i] = sl[r0 + i] * f[i] + rs;
            }
            *(float4*)&sP[(r0 + i) * SP_STRIDE + c0] =
                make_float4(acc[i][0], acc[i][1], acc[i][2], acc[i][3]);
        }
        __syncthreads();

#pragma unroll
        for (int i = 0; i < 4; i++)
#pragma unroll
            for (int d = 0; d < 8; d++) o[i][d] *= f[i];

#pragma unroll 2
        for (int c = 0; c < BC; c++) {
            float pv[4];
#pragma unroll
            for (int i = 0; i < 4; i++) pv[i] = sP[(r0 + i) * SP_STRIDE + c];
            float4 v1 = *(const float4*)&sV[c * SV_STRIDE + d0];
            float4 v2 = *(const float4*)&sV[c * SV_STRIDE + d0 + 4];
#pragma unroll
            for (int i = 0; i < 4; i++) {
                o[i][0] += pv[i] * v1.x;
                o[i][1] += pv[i] * v1.y;
                o[i][2] += pv[i] * v1.z;
                o[i][3] += pv[i] * v1.w;
                o[i][4] += pv[i] * v2.x;
                o[i][5] += pv[i] * v2.y;
                o[i][6] += pv[i] * v2.z;
                o[i][7] += pv[i] * v2.w;
            }
        }
        __syncthreads();
    }

#pragma unroll
    for (int i = 0; i < 4; i++) {
        const float inv = 1.0f / sl[r0 + i];
        const int srow = q0 + r0 + i;
        float* op = g_O + (((size_t)b * SEQ + srow) * NHEADS + h) * DHEAD + d0;
        *(float4*)op       = make_float4(o[i][0] * inv, o[i][1] * inv, o[i][2] * inv, o[i][3] * inv);
        *(float4*)(op + 4) = make_float4(o[i][4] * inv, o[i][5] * inv, o[i][6] * inv, o[i][7] * inv);
    }
}

// ---------------------------------------------------------------------------
// Launch
// ---------------------------------------------------------------------------
extern "C" void kernel_launch(void* const* d_in, const int* in_sizes, int n_in,
                              void* d_out, int out_size)
{
    const float* x    = (const float*)d_in[0];
    const float* Wqkv = (const float*)d_in[1];
    const float* Wout = (const float*)d_in[2];
    float* out = (float*)d_out;

    const int M = BATCH * SEQ;          // 4096

    cudaFuncSetAttribute(gemm_mma<1>, cudaFuncAttributeMaxDynamicSharedMemorySize, GEMM_SMEM);
    cudaFuncSetAttribute(gemm_mma<0>, cudaFuncAttributeMaxDynamicSharedMemorySize, GEMM_SMEM);
    cudaFuncSetAttribute(flash_attn_kernel, cudaFuncAttributeMaxDynamicSharedMemorySize, ATT_SMEM_BYTES);

    // Stage 1: QKV projection on tensor cores (scatter epilogue)
    gemm_mma<1><<<dim3((3 * DMODEL) / 128, M / 128), 256, GEMM_SMEM>>>(
        x, Wqkv, nullptr, 3 * DMODEL);

    // Stage 2: flash attention (fp32 SIMT)
    flash_attn_kernel<<<dim3(SEQ / BR, BATCH * NHEADS), 256, ATT_SMEM_BYTES>>>();

    // Stage 3: output projection on tensor cores
    float* oPtr = nullptr;
    cudaGetSymbolAddress((void**)&oPtr, g_O);
    gemm_mma<0><<<dim3(DMODEL / 128, M / 128), 256, GEMM_SMEM>>>(
        oPtr, Wout, out, M ? DMODEL : DMODEL);
}

// round 4
// speedup vs baseline: 3.3848x; 1.6310x over previous
#include <cuda_runtime.h>
#include <cstdint>

// Problem constants
#define BATCH   2
#define SEQ     2048
#define DMODEL  2048
#define NHEADS  16
#define DHEAD   128

// ---------------------------------------------------------------------------
// Scratch (alloc-free: __device__ globals)
// ---------------------------------------------------------------------------
__device__ float g_Q[(size_t)BATCH * NHEADS * SEQ * DHEAD];
__device__ float g_K[(size_t)BATCH * NHEADS * SEQ * DHEAD];
__device__ float g_V[(size_t)BATCH * NHEADS * SEQ * DHEAD];
__device__ float g_O[(size_t)BATCH * SEQ * DMODEL];

__device__ __forceinline__ uint32_t f2tf(float x) {
    uint32_t r;
    asm("cvt.rna.tf32.f32 %0, %1;" : "=r"(r) : "f"(x));
    return r;
}

__device__ __forceinline__ void mma_tf32(float* d, const uint32_t* a, const uint32_t* b) {
    asm volatile(
        "mma.sync.aligned.m16n8k8.row.col.f32.tf32.tf32.f32 "
        "{%0,%1,%2,%3}, {%4,%5,%6,%7}, {%8,%9}, {%0,%1,%2,%3};"
        : "+f"(d[0]), "+f"(d[1]), "+f"(d[2]), "+f"(d[3])
        : "r"(a[0]), "r"(a[1]), "r"(a[2]), "r"(a[3]), "r"(b[0]), "r"(b[1]));
}

// ---------------------------------------------------------------------------
// tf32 mma.sync NT GEMM (unchanged from round 3)
// ---------------------------------------------------------------------------
#define KC  32
#define NCH (DMODEL / KC)                  // 64
#define AFRAG_BYTES (32 * 33 * 16)         // 16896
#define BFRAG_BYTES (64 * 33 * 8)          // 16896
#define BUFBYTES (AFRAG_BYTES + BFRAG_BYTES)
#define GEMM_SMEM (2 * BUFBYTES)           // 67584

template <int MODE>
__global__ void __launch_bounds__(256)
gemm_mma(const float* __restrict__ A, const float* __restrict__ B,
         float* __restrict__ C, int N)
{
    extern __shared__ char smemc[];
    const int tid = threadIdx.x;
    const int wid = tid >> 5;
    const int lid = tid & 31;
    const int wm  = wid & 1;
    const int wn  = wid >> 1;
    const int m0  = blockIdx.y * 128;
    const int n0  = blockIdx.x * 128;

    float acc[4][4][4];
#pragma unroll
    for (int i = 0; i < 4; i++)
#pragma unroll
        for (int j = 0; j < 4; j++)
#pragma unroll
            for (int v = 0; v < 4; v++) acc[i][j][v] = 0.0f;

    const float* Ab = A + (size_t)m0 * DMODEL;
    const float* Bb = B + (size_t)n0 * DMODEL;

    float4 ar[4], br[4];

    auto ldg_chunk = [&](int k0) {
#pragma unroll
        for (int it = 0; it < 4; it++) {
            const int idx = tid + it * 256;
            const int row = idx >> 3;
            const int c4  = idx & 7;
            ar[it] = *(const float4*)(Ab + (size_t)row * DMODEL + k0 + c4 * 4);
            br[it] = *(const float4*)(Bb + (size_t)row * DMODEL + k0 + c4 * 4);
        }
    };

    auto sts_chunk = [&](int buf) {
        char* bp = smemc + buf * BUFBYTES;
#pragma unroll
        for (int it = 0; it < 4; it++) {
            const int idx = tid + it * 256;
            const int row = idx >> 3;
            const int c4  = idx & 7;
            const int ks  = c4 >> 1;
            {
                const int gm   = row >> 4;
                const int r    = row & 7;
                const int slot = ((c4 & 1) << 1) | ((row >> 3) & 1);
                uint32_t* p = (uint32_t*)(bp + ((gm * 4 + ks) * 33 + r * 4) * 16 + slot * 4);
                p[0]  = f2tf(ar[it].x);
                p[4]  = f2tf(ar[it].y);
                p[8]  = f2tf(ar[it].z);
                p[12] = f2tf(ar[it].w);
            }
            {
                const int gn  = row >> 3;
                const int nl  = (row & 7) * 4;
                const int slb = c4 & 1;
                uint32_t* q = (uint32_t*)(bp + AFRAG_BYTES + ((gn * 4 + ks) * 33 + nl) * 8 + slb * 4);
                q[0] = f2tf(br[it].x);
                q[2] = f2tf(br[it].y);
                q[4] = f2tf(br[it].z);
                q[6] = f2tf(br[it].w);
            }
        }
    };

    ldg_chunk(0);
    sts_chunk(0);
    __syncthreads();

    for (int c = 0; c < NCH; ++c) {
        const int buf = c & 1;
        if (c + 1 < NCH) ldg_chunk((c + 1) * KC);

        const uint32_t* fA = (const uint32_t*)(smemc + buf * BUFBYTES);
        const uint32_t* fB = (const uint32_t*)(smemc + buf * BUFBYTES + AFRAG_BYTES);
#pragma unroll
        for (int ks = 0; ks < 4; ks++) {
            uint32_t a[4][4], b[4][2];
#pragma unroll
            for (int mt = 0; mt < 4; mt++)
                *(uint4*)a[mt] = *(const uint4*)&fA[(((wm * 4 + mt) * 4 + ks) * 33 + lid) * 4];
#pragma unroll
            for (int nt = 0; nt < 4; nt++)
                *(uint2*)b[nt] = *(const uint2*)&fB[(((wn * 4 + nt) * 4 + ks) * 33 + lid) * 2];
#pragma unroll
            for (int mt = 0; mt < 4; mt++)
#pragma unroll
                for (int nt = 0; nt < 4; nt++)
                    mma_tf32(acc[mt][nt], a[mt], b[nt]);
        }

        if (c + 1 < NCH) sts_chunk(buf ^ 1);
        __syncthreads();
    }

    const int lr = lid >> 2;
    const int lc = (lid & 3) * 2;
#pragma unroll
    for (int mt = 0; mt < 4; mt++) {
        const int mrow = wm * 64 + mt * 16 + lr;
#pragma unroll
        for (int nt = 0; nt < 4; nt++) {
            const int ncol = wn * 32 + nt * 8 + lc;
            if (MODE == 0) {
                float* dst = C + (size_t)(m0 + mrow) * N + n0 + ncol;
                *(float2*)dst                    = make_float2(acc[mt][nt][0], acc[mt][nt][1]);
                *(float2*)(dst + (size_t)8 * N)  = make_float2(acc[mt][nt][2], acc[mt][nt][3]);
            } else {
                const int t = n0 >> 11;
                const int h = (n0 >> 7) & (NHEADS - 1);
                const int b = m0 >> 11;
                const int s = (m0 & (SEQ - 1)) + mrow;
                float* basep = (t == 0 ? g_Q : (t == 1 ? g_K : g_V));
                float* dst = basep + ((size_t)(b * NHEADS + h) * SEQ + s) * DHEAD + ncol;
                *(float2*)dst                 = make_float2(acc[mt][nt][0], acc[mt][nt][1]);
                *(float2*)(dst + 8 * DHEAD)   = make_float2(acc[mt][nt][2], acc[mt][nt][3]);
            }
        }
    }
}

// ---------------------------------------------------------------------------
// Flash attention on tensor cores (tf32 mma.sync), causal.
// CTA: 256 threads (8 warps). Q tile = 128 rows (warp w owns rows w*16..+15),
// KV tile = 64. Q staged once in A-frag layout; K/V staged per block in
// B-frag layout; P round-trips through per-warp smem as A-frags.
// ---------------------------------------------------------------------------
#define ABR 128
#define ABC 64

// smem (bytes)
#define AQ_OFF   0
#define AQ_BYTES (128 * 132 * 4)           // 128 blocks x 132 u32 = 67584
#define AK_OFF   (AQ_OFF + AQ_BYTES)
#define AK_BYTES (128 * 66 * 4)            // 33792
#define AV_OFF   (AK_OFF + AK_BYTES)
#define AV_BYTES (128 * 66 * 4)            // 33792
#define AP_OFF   (AV_OFF + AV_BYTES)
#define AP_BYTES (8 * 16 * 68 * 4)         // 34816
#define ATT2_SMEM (AP_OFF + AP_BYTES)      // 169984

__global__ void __launch_bounds__(256, 1)
flash_attn_mma()
{
    extern __shared__ char sm[];
    uint32_t* QA = (uint32_t*)(sm + AQ_OFF);   // block (kt*8+w)*132 + lane*4 + slot
    uint32_t* KB = (uint32_t*)(sm + AK_OFF);   // block (kt*8+nt)*66 + lane*2 + slot
    uint32_t* VB = (uint32_t*)(sm + AV_OFF);   // block (nt*8+ks)*66 + lane*2 + slot

    const int tid = threadIdx.x;
    const int wid = tid >> 5;
    const int lid = tid & 31;
    const int qb  = gridDim.x - 1 - blockIdx.x;   // big tiles first
    const int bh  = blockIdx.y;
    const int q0  = qb * ABR;
    const int b   = bh >> 4;
    const int h   = bh & (NHEADS - 1);

    const float* Qg = g_Q + (size_t)bh * SEQ * DHEAD;
    const float* Kg = g_K + (size_t)bh * SEQ * DHEAD;
    const float* Vg = g_V + (size_t)bh * SEQ * DHEAD;

    // ---- stage Q (128x128) once, into A-fragment layout ----
#pragma unroll
    for (int it = 0; it < 16; it++) {
        const int idx = tid + it * 256;          // 4096 float4
        const int d4  = idx >> 7;                // 0..31
        const int r   = idx & 127;               // 0..127
        float4 v = *(const float4*)(Qg + (size_t)(q0 + r) * DHEAD + d4 * 4);
        const int w    = r >> 4;
        const int kt   = d4 >> 1;
        const int slot = ((d4 & 1) ? 2 : 0) + ((r >> 3) & 1);
        uint32_t* p = &QA[(kt * 8 + w) * 132 + ((r & 7) * 4) * 4 + slot];
        p[0]  = f2tf(v.x);
        p[4]  = f2tf(v.y);
        p[8]  = f2tf(v.z);
        p[12] = f2tf(v.w);
    }

    const int lr = lid >> 2;                     // 0..7
    const int lc = lid & 3;                      // 0..3
    uint32_t* Pw = (uint32_t*)(sm + AP_OFF) + wid * (16 * 68);

    float o[16][4];
#pragma unroll
    for (int nt = 0; nt < 16; nt++)
#pragma unroll
        for (int v = 0; v < 4; v++) o[nt][v] = 0.0f;

    float m0 = -1e30f, m1 = -1e30f, l0 = 0.0f, l1 = 0.0f;
    const float scale = 0.08838834764831845f;    // 1/sqrt(128)
    const int row0 = q0 + wid * 16 + lr;
    const int row1 = row0 + 8;

    const int nkb = 2 * qb + 2;
    for (int kb = 0; kb < nkb; kb++) {
        const int k0 = kb * ABC;
        __syncthreads();                          // prev iter done with KB/VB (and Q staged)

        // ---- stage K/V block (64x128) into B-frag layouts ----
#pragma unroll
        for (int it = 0; it < 8; it++) {
            const int idx = tid + it * 256;       // 2048 float4
            const int d4  = idx >> 6;             // 0..31
            const int s   = idx & 63;             // 0..63
            const int d   = d4 * 4;
            float4 kv = *(const float4*)(Kg + (size_t)(k0 + s) * DHEAD + d4 * 4);
            {
                const int blockid = (d4 >> 1) * 8 + (s >> 3);
                const int slot = (d4 & 1);        // (d&7)<4 ? 0 : 1
                uint32_t* p = &KB[blockid * 66 + ((s & 7) * 4) * 2 + slot];
                p[0] = f2tf(kv.x);
                p[2] = f2tf(kv.y);
                p[4] = f2tf(kv.z);
                p[6] = f2tf(kv.w);
            }
            float4 vv = *(const float4*)(Vg + (size_t)(k0 + s) * DHEAD + d4 * 4);
            {
                const int blockid = (d4 >> 1) * 8 + (s >> 3);   // nt*8+ks, nt=d>>3
                const int slot = ((s & 7) < 4) ? 0 : 1;
                const int lane0 = (d4 & 1) * 16 + (s & 3);
                uint32_t* p = &VB[blockid * 66 + lane0 * 2 + slot];
                p[0]  = f2tf(vv.x);
                p[8]  = f2tf(vv.y);                // lane += 4 per elem
                p[16] = f2tf(vv.z);
                p[24] = f2tf(vv.w);
            }
        }
        __syncthreads();

        // ---- S = Q . K^T : 16 rows x 64 cols per warp ----
        float s[8][4];
#pragma unroll
        for (int nt = 0; nt < 8; nt++)
#pragma unroll
            for (int v = 0; v < 4; v++) s[nt][v] = 0.0f;

#pragma unroll
        for (int kt = 0; kt < 16; kt++) {
            uint32_t a[4];
            *(uint4*)a = *(const uint4*)&QA[(kt * 8 + wid) * 132 + lid * 4];
#pragma unroll
            for (int nt = 0; nt < 8; nt++) {
                uint32_t bf[2];
                *(uint2*)bf = *(const uint2*)&KB[(kt * 8 + nt) * 66 + lid * 2];
                mma_tf32(s[nt], a, bf);
            }
        }

        // ---- scale + causal mask + online softmax (register-resident) ----
        const bool domask = (kb >= 2 * qb);
        float ml0 = -1e30f, ml1 = -1e30f;
#pragma unroll
        for (int nt = 0; nt < 8; nt++) {
            const int c0 = k0 + nt * 8 + lc * 2;
            s[nt][0] *= scale; s[nt][1] *= scale;
            s[nt][2] *= scale; s[nt][3] *= scale;
            if (domask) {
                if (c0     > row0) s[nt][0] = -1e30f;
                if (c0 + 1 > row0) s[nt][1] = -1e30f;
                if (c0     > row1) s[nt][2] = -1e30f;
                if (c0 + 1 > row1) s[nt][3] = -1e30f;
            }
            ml0 = fmaxf(ml0, fmaxf(s[nt][0], s[nt][1]));
            ml1 = fmaxf(ml1, fmaxf(s[nt][2], s[nt][3]));
        }
        ml0 = fmaxf(ml0, __shfl_xor_sync(0xffffffffu, ml0, 1));
        ml0 = fmaxf(ml0, __shfl_xor_sync(0xffffffffu, ml0, 2));
        ml1 = fmaxf(ml1, __shfl_xor_sync(0xffffffffu, ml1, 1));
        ml1 = fmaxf(ml1, __shfl_xor_sync(0xffffffffu, ml1, 2));

        const float mn0 = fmaxf(m0, ml0);
        const float mn1 = fmaxf(m1, ml1);
        const float f0 = __expf(m0 - mn0);
        const float f1 = __expf(m1 - mn1);
        m0 = mn0; m1 = mn1;

        float rs0 = 0.0f, rs1 = 0.0f;
#pragma unroll
        for (int nt = 0; nt < 8; nt++) {
            s[nt][0] = __expf(s[nt][0] - mn0);
            s[nt][1] = __expf(s[nt][1] - mn0);
            s[nt][2] = __expf(s[nt][2] - mn1);
            s[nt][3] = __expf(s[nt][3] - mn1);
            rs0 += s[nt][0] + s[nt][1];
            rs1 += s[nt][2] + s[nt][3];
        }
        rs0 += __shfl_xor_sync(0xffffffffu, rs0, 1);
        rs0 += __shfl_xor_sync(0xffffffffu, rs0, 2);
        rs1 += __shfl_xor_sync(0xffffffffu, rs1, 1);
        rs1 += __shfl_xor_sync(0xffffffffu, rs1, 2);
        l0 = l0 * f0 + rs0;
        l1 = l1 * f1 + rs1;

#pragma unroll
        for (int nt = 0; nt < 16; nt++) {
            o[nt][0] *= f0; o[nt][1] *= f0;
            o[nt][2] *= f1; o[nt][3] *= f1;
        }

        // ---- P -> per-warp smem (A-frag source) ----
#pragma unroll
        for (int nt = 0; nt < 8; nt++) {
            *(uint2*)&Pw[lr * 68 + nt * 8 + lc * 2] =
                make_uint2(f2tf(s[nt][0]), f2tf(s[nt][1]));
            *(uint2*)&Pw[(lr + 8) * 68 + nt * 8 + lc * 2] =
                make_uint2(f2tf(s[nt][2]), f2tf(s[nt][3]));
        }
        __syncwarp();

        // ---- O += P . V ----
#pragma unroll
        for (int ks = 0; ks < 8; ks++) {
            uint32_t a[4];
            a[0] = Pw[lr * 68 + ks * 8 + lc];
            a[1] = Pw[(lr + 8) * 68 + ks * 8 + lc];
            a[2] = Pw[lr * 68 + ks * 8 + lc + 4];
            a[3] = Pw[(lr + 8) * 68 + ks * 8 + lc + 4];
#pragma unroll
            for (int nt = 0; nt < 16; nt++) {
                uint32_t bf[2];
                *(uint2*)bf = *(const uint2*)&VB[(nt * 8 + ks) * 66 + lid * 2];
                mma_tf32(o[nt], a, bf);
            }
        }
    }

    // ---- epilogue ----
    const float inv0 = 1.0f / l0;
    const float inv1 = 1.0f / l1;
    float* O0 = g_O + (((size_t)b * SEQ + row0) * NHEADS + h) * DHEAD;
    float* O1 = g_O + (((size_t)b * SEQ + row1) * NHEADS + h) * DHEAD;
#pragma unroll
    for (int nt = 0; nt < 16; nt++) {
        const int col = nt * 8 + lc * 2;
        *(float2*)(O0 + col) = make_float2(o[nt][0] * inv0, o[nt][1] * inv0);
        *(float2*)(O1 + col) = make_float2(o[nt][2] * inv1, o[nt][3] * inv1);
    }
}

// ---------------------------------------------------------------------------
// Launch
// ---------------------------------------------------------------------------
extern "C" void kernel_launch(void* const* d_in, const int* in_sizes, int n_in,
                              void* d_out, int out_size)
{
    const float* x    = (const float*)d_in[0];
    const float* Wqkv = (const float*)d_in[1];
    const float* Wout = (const float*)d_in[2];
    float* out = (float*)d_out;

    const int M = BATCH * SEQ;          // 4096

    cudaFuncSetAttribute(gemm_mma<1>, cudaFuncAttributeMaxDynamicSharedMemorySize, GEMM_SMEM);
    cudaFuncSetAttribute(gemm_mma<0>, cudaFuncAttributeMaxDynamicSharedMemorySize, GEMM_SMEM);
    cudaFuncSetAttribute(flash_attn_mma, cudaFuncAttributeMaxDynamicSharedMemorySize, ATT2_SMEM);

    // Stage 1: QKV projection (tensor cores, scatter epilogue)
    gemm_mma<1><<<dim3((3 * DMODEL) / 128, M / 128), 256, GEMM_SMEM>>>(
        x, Wqkv, nullptr, 3 * DMODEL);

    // Stage 2: flash attention (tensor cores)
    flash_attn_mma<<<dim3(SEQ / ABR, BATCH * NHEADS), 256, ATT2_SMEM>>>();

    // Stage 3: output projection (tensor cores)
    float* oPtr = nullptr;
    cudaGetSymbolAddress((void**)&oPtr, g_O);
    gemm_mma<0><<<dim3(DMODEL / 128, M / 128), 256, GEMM_SMEM>>>(
        oPtr, Wout, out, DMODEL);
}

// round 5
// speedup vs baseline: 3.6156x; 1.0682x over previous
#include <cuda_runtime.h>
#include <cstdint>

// Problem constants
#define BATCH   2
#define SEQ     2048
#define DMODEL  2048
#define NHEADS  16
#define DHEAD   128

#define NCH 64                     // K chunks of 32 (K = 2048)

// ---------------------------------------------------------------------------
// Scratch (alloc-free: __device__ globals)
// ---------------------------------------------------------------------------
__device__ float g_Q[(size_t)BATCH * NHEADS * SEQ * DHEAD];
__device__ float g_K[(size_t)BATCH * NHEADS * SEQ * DHEAD];
__device__ float g_V[(size_t)BATCH * NHEADS * SEQ * DHEAD];
__device__ float g_O[(size_t)BATCH * SEQ * DMODEL];

// tf32 pre-converted fragment-layout operands
// A-frag tile (per 128 rows x 32 k): 32 blocks x 32 lanes x 4 u32 = 4096 u32
// B-frag tile (per 128 cols x 32 k): 64 blocks x 32 lanes x 2 u32 = 4096 u32
__device__ __align__(128) uint32_t g_xf [(size_t)32 * NCH * 4096];   // x      [4096,2048]
__device__ __align__(128) uint32_t g_of [(size_t)32 * NCH * 4096];   // g_O    [4096,2048]
__device__ __align__(128) uint32_t g_wqf[(size_t)48 * NCH * 4096];   // W_qkv  [6144,2048]
__device__ __align__(128) uint32_t g_wof[(size_t)16 * NCH * 4096];   // W_out  [2048,2048]

__device__ __forceinline__ uint32_t f2tf(float x) {
    uint32_t r;
    asm("cvt.rna.tf32.f32 %0, %1;" : "=r"(r) : "f"(x));
    return r;
}

__device__ __forceinline__ void mma_tf32(float* d, const uint32_t* a, const uint32_t* b) {
    asm volatile(
        "mma.sync.aligned.m16n8k8.row.col.f32.tf32.tf32.f32 "
        "{%0,%1,%2,%3}, {%4,%5,%6,%7}, {%8,%9}, {%0,%1,%2,%3};"
        : "+f"(d[0]), "+f"(d[1]), "+f"(d[2]), "+f"(d[3])
        : "r"(a[0]), "r"(a[1]), "r"(a[2]), "r"(a[3]), "r"(b[0]), "r"(b[1]));
}

__device__ __forceinline__ void cpa16(uint32_t dst, const void* src) {
    asm volatile("cp.async.cg.shared.global [%0], [%1], 16;"
                 :: "r"(dst), "l"(src) : "memory");
}
#define CPA_COMMIT() asm volatile("cp.async.commit_group;" ::: "memory")
#define CPA_WAIT(n)  asm volatile("cp.async.wait_group %0;" :: "n"(n) : "memory")

__device__ __forceinline__ uint32_t smem_u32(const void* p) {
    uint32_t a;
    asm("{ .reg .u64 t; cvta.to.shared.u64 t, %1; cvt.u32.u64 %0, t; }"
        : "=r"(a) : "l"(p));
    return a;
}

// ---------------------------------------------------------------------------
// Conversion kernels: fp32 row-major -> tf32 fragment layout
// grid = (NCH, rows/128), 256 threads
// ---------------------------------------------------------------------------
__global__ void __launch_bounds__(256)
conv_A(const float* __restrict__ src, uint32_t* __restrict__ dst)
{
    __shared__ float s[128][33];
    const int ch = blockIdx.x, mb = blockIdx.y, tid = threadIdx.x;
    const float* base = src + (size_t)mb * 128 * DMODEL + ch * 32;
#pragma unroll
    for (int i = 0; i < 4; i++) {
        const int idx = tid + i * 256;
        const int row = idx >> 3, c4 = idx & 7;
        float4 v = *(const float4*)(base + (size_t)row * DMODEL + c4 * 4);
        s[row][c4 * 4 + 0] = v.x; s[row][c4 * 4 + 1] = v.y;
        s[row][c4 * 4 + 2] = v.z; s[row][c4 * 4 + 3] = v.w;
    }
    __syncthreads();
    uint32_t* out = dst + ((size_t)mb * NCH + ch) * 4096;
#pragma unroll
    for (int i = 0; i < 4; i++) {
        const int u = tid + i * 256;
        const int blk = u >> 5, lane = u & 31;
        const int gm = blk >> 2, ks = blk & 3;
        const int r = lane >> 2, kl = lane & 3;
        uint4 w = make_uint4(
            f2tf(s[gm * 16 + r    ][ks * 8 + kl    ]),
            f2tf(s[gm * 16 + r + 8][ks * 8 + kl    ]),
            f2tf(s[gm * 16 + r    ][ks * 8 + kl + 4]),
            f2tf(s[gm * 16 + r + 8][ks * 8 + kl + 4]));
        *(uint4*)(out + (size_t)u * 4) = w;
    }
}

__global__ void __launch_bounds__(256)
conv_B(const float* __restrict__ src, uint32_t* __restrict__ dst)
{
    __shared__ float s[128][33];
    const int ch = blockIdx.x, nb = blockIdx.y, tid = threadIdx.x;
    const float* base = src + (size_t)nb * 128 * DMODEL + ch * 32;
#pragma unroll
    for (int i = 0; i < 4; i++) {
        const int idx = tid + i * 256;
        const int row = idx >> 3, c4 = idx & 7;
        float4 v = *(const float4*)(base + (size_t)row * DMODEL + c4 * 4);
        s[row][c4 * 4 + 0] = v.x; s[row][c4 * 4 + 1] = v.y;
        s[row][c4 * 4 + 2] = v.z; s[row][c4 * 4 + 3] = v.w;
    }
    __syncthreads();
    uint32_t* out = dst + ((size_t)nb * NCH + ch) * 4096;
#pragma unroll
    for (int i = 0; i < 8; i++) {
        const int u = tid + i * 256;
        const int blk = u >> 5, lane = u & 31;
        const int gn = blk >> 2, ks = blk & 3;
        const int n8 = lane >> 2, kl = lane & 3;
        uint2 w = make_uint2(
            f2tf(s[gn * 8 + n8][ks * 8 + kl    ]),
            f2tf(s[gn * 8 + n8][ks * 8 + kl + 4]));
        *(uint2*)(out + (size_t)u * 2) = w;
    }
}

// ---------------------------------------------------------------------------
// Fragment-fed tf32 GEMM: C[m,n] = sum_k A[m,k]*B[n,k], K = 2048.
// CTA 128(m) x 256(n), 256 threads, 8 warps (2m x 4n), warp tile 64x64.
// cp.async double-buffered fragment tiles. Pure MMA inner loop.
// MODE 0: C row-major [M, 2048].  MODE 1: scatter QKV (fp32).
// ---------------------------------------------------------------------------
#define GF_SMEM (2 * 12288 * 4)    // 98304 bytes

template <int MODE>
__global__ void __launch_bounds__(256)
gemm_f(const uint32_t* __restrict__ Af, const uint32_t* __restrict__ Bf,
       float* __restrict__ C)
{
    extern __shared__ uint32_t us[];
    const int tid = threadIdx.x;
    const int wid = tid >> 5;
    const int lid = tid & 31;
    const int wm  = wid & 1;              // 0..1 : 64-row slab
    const int wn  = wid >> 1;             // 0..3 : 64-col slab
    const int mb  = blockIdx.y;           // 128-row tile
    const int nbx = blockIdx.x;           // 256-col tile
    const uint32_t sb = smem_u32(us);

    float acc[4][8][4];
#pragma unroll
    for (int i = 0; i < 4; i++)
#pragma unroll
        for (int j = 0; j < 8; j++)
#pragma unroll
            for (int v = 0; v < 4; v++) acc[i][j][v] = 0.0f;

    auto issue = [&](int c, int buf) {
        const uint32_t sA = sb + buf * 49152;
        const uint32_t sB = sA + 16384;
        const uint32_t* gA  = Af + ((size_t)mb * NCH + c) * 4096;
        const uint32_t* gB0 = Bf + ((size_t)(2 * nbx)     * NCH + c) * 4096;
        const uint32_t* gB1 = Bf + ((size_t)(2 * nbx + 1) * NCH + c) * 4096;
#pragma unroll
        for (int i = 0; i < 4; i++) {
            const int o = tid + i * 256;
            cpa16(sA + o * 16, gA + (size_t)o * 4);
        }
#pragma unroll
        for (int i = 0; i < 4; i++) {
            const int o = tid + i * 256;
            cpa16(sB + o * 16, gB0 + (size_t)o * 4);
        }
#pragma unroll
        for (int i = 0; i < 4; i++) {
            const int o = tid + i * 256;
            cpa16(sB + 16384 + o * 16, gB1 + (size_t)o * 4);
        }
        CPA_COMMIT();
    };

    issue(0, 0);

    for (int c = 0; c < NCH; ++c) {
        const int buf = c & 1;
        if (c + 1 < NCH) { issue(c + 1, buf ^ 1); CPA_WAIT(1); }
        else             { CPA_WAIT(0); }
        __syncthreads();

        const uint32_t* uA = us + buf * 12288;
        const uint32_t* uB = uA + 4096;
#pragma unroll
        for (int ks = 0; ks < 4; ks++) {
            uint32_t a[4][4], b[8][2];
#pragma unroll
            for (int mt = 0; mt < 4; mt++)
                *(uint4*)a[mt] = *(const uint4*)&uA[(((wm * 4 + mt) * 4 + ks) * 32 + lid) * 4];
#pragma unroll
            for (int nt = 0; nt < 8; nt++) {
                const int gn = wn * 8 + nt;
                *(uint2*)b[nt] = *(const uint2*)
                    &uB[((gn >> 4) * 4096) + (((gn & 15) * 4 + ks) * 32 + lid) * 2];
            }
#pragma unroll
            for (int mt = 0; mt < 4; mt++)
#pragma unroll
                for (int nt = 0; nt < 8; nt++)
                    mma_tf32(acc[mt][nt], a[mt], b[nt]);
        }
        __syncthreads();
    }

    // ---- epilogue ----
    const int lr  = lid >> 2;
    const int lc2 = (lid & 3) * 2;
    const int m0  = mb * 128;
    const int n0  = nbx * 256;
#pragma unroll
    for (int mt = 0; mt < 4; mt++) {
        const int m = m0 + wm * 64 + mt * 16 + lr;
#pragma unroll
        for (int nt = 0; nt < 8; nt++) {
            const int cg = n0 + wn * 64 + nt * 8 + lc2;
            if (MODE == 0) {
                float* dst = C + (size_t)m * DMODEL + cg;
                *(float2*)dst                         = make_float2(acc[mt][nt][0], acc[mt][nt][1]);
                *(float2*)(dst + (size_t)8 * DMODEL)  = make_float2(acc[mt][nt][2], acc[mt][nt][3]);
            } else {
                const int t = cg >> 11;                 // 0=Q,1=K,2=V (uniform per CTA)
                const int h = (cg >> 7) & (NHEADS - 1);
                const int d = cg & (DHEAD - 1);
                const int b = m >> 11;
                const int s = m & (SEQ - 1);
                float* basep = (t == 0 ? g_Q : (t == 1 ? g_K : g_V));
                float* dst = basep + ((size_t)(b * NHEADS + h) * SEQ + s) * DHEAD + d;
                *(float2*)dst                = make_float2(acc[mt][nt][0], acc[mt][nt][1]);
                *(float2*)(dst + 8 * DHEAD)  = make_float2(acc[mt][nt][2], acc[mt][nt][3]);
            }
        }
    }
}

// ---------------------------------------------------------------------------
// Flash attention on tensor cores (tf32 mma.sync), causal. (unchanged, round 4)
// ---------------------------------------------------------------------------
#define ABR 128
#define ABC 64

#define AQ_OFF   0
#define AQ_BYTES (128 * 132 * 4)
#define AK_OFF   (AQ_OFF + AQ_BYTES)
#define AK_BYTES (128 * 66 * 4)
#define AV_OFF   (AK_OFF + AK_BYTES)
#define AV_BYTES (128 * 66 * 4)
#define AP_OFF   (AV_OFF + AV_BYTES)
#define AP_BYTES (8 * 16 * 68 * 4)
#define ATT2_SMEM (AP_OFF + AP_BYTES)

__global__ void __launch_bounds__(256, 1)
flash_attn_mma()
{
    extern __shared__ char sm[];
    uint32_t* QA = (uint32_t*)(sm + AQ_OFF);
    uint32_t* KB = (uint32_t*)(sm + AK_OFF);
    uint32_t* VB = (uint32_t*)(sm + AV_OFF);

    const int tid = threadIdx.x;
    const int wid = tid >> 5;
    const int lid = tid & 31;
    const int qb  = gridDim.x - 1 - blockIdx.x;
    const int bh  = blockIdx.y;
    const int q0  = qb * ABR;
    const int b   = bh >> 4;
    const int h   = bh & (NHEADS - 1);

    const float* Qg = g_Q + (size_t)bh * SEQ * DHEAD;
    const float* Kg = g_K + (size_t)bh * SEQ * DHEAD;
    const float* Vg = g_V + (size_t)bh * SEQ * DHEAD;

#pragma unroll
    for (int it = 0; it < 16; it++) {
        const int idx = tid + it * 256;
        const int d4  = idx >> 7;
        const int r   = idx & 127;
        float4 v = *(const float4*)(Qg + (size_t)(q0 + r) * DHEAD + d4 * 4);
        const int w    = r >> 4;
        const int kt   = d4 >> 1;
        const int slot = ((d4 & 1) ? 2 : 0) + ((r >> 3) & 1);
        uint32_t* p = &QA[(kt * 8 + w) * 132 + ((r & 7) * 4) * 4 + slot];
        p[0]  = f2tf(v.x);
        p[4]  = f2tf(v.y);
        p[8]  = f2tf(v.z);
        p[12] = f2tf(v.w);
    }

    const int lr = lid >> 2;
    const int lc = lid & 3;
    uint32_t* Pw = (uint32_t*)(sm + AP_OFF) + wid * (16 * 68);

    float o[16][4];
#pragma unroll
    for (int nt = 0; nt < 16; nt++)
#pragma unroll
        for (int v = 0; v < 4; v++) o[nt][v] = 0.0f;

    float m0 = -1e30f, m1 = -1e30f, l0 = 0.0f, l1 = 0.0f;
    const float scale = 0.08838834764831845f;
    const int row0 = q0 + wid * 16 + lr;
    const int row1 = row0 + 8;

    const int nkb = 2 * qb + 2;
    for (int kb = 0; kb < nkb; kb++) {
        const int k0 = kb * ABC;
        __syncthreads();

#pragma unroll
        for (int it = 0; it < 8; it++) {
            const int idx = tid + it * 256;
            const int d4  = idx >> 6;
            const int s   = idx & 63;
            float4 kv = *(const float4*)(Kg + (size_t)(k0 + s) * DHEAD + d4 * 4);
            {
                const int blockid = (d4 >> 1) * 8 + (s >> 3);
                const int slot = (d4 & 1);
                uint32_t* p = &KB[blockid * 66 + ((s & 7) * 4) * 2 + slot];
                p[0] = f2tf(kv.x);
                p[2] = f2tf(kv.y);
                p[4] = f2tf(kv.z);
                p[6] = f2tf(kv.w);
            }
            float4 vv = *(const float4*)(Vg + (size_t)(k0 + s) * DHEAD + d4 * 4);
            {
                const int blockid = (d4 >> 1) * 8 + (s >> 3);
                const int slot = ((s & 7) < 4) ? 0 : 1;
                const int lane0 = (d4 & 1) * 16 + (s & 3);
                uint32_t* p = &VB[blockid * 66 + lane0 * 2 + slot];
                p[0]  = f2tf(vv.x);
                p[8]  = f2tf(vv.y);
                p[16] = f2tf(vv.z);
                p[24] = f2tf(vv.w);
            }
        }
        __syncthreads();

        float s[8][4];
#pragma unroll
        for (int nt = 0; nt < 8; nt++)
#pragma unroll
            for (int v = 0; v < 4; v++) s[nt][v] = 0.0f;

#pragma unroll
        for (int kt = 0; kt < 16; kt++) {
            uint32_t a[4];
            *(uint4*)a = *(const uint4*)&QA[(kt * 8 + wid) * 132 + lid * 4];
#pragma unroll
            for (int nt = 0; nt < 8; nt++) {
                uint32_t bf[2];
                *(uint2*)bf = *(const uint2*)&KB[(kt * 8 + nt) * 66 + lid * 2];
                mma_tf32(s[nt], a, bf);
            }
        }

        const bool domask = (kb >= 2 * qb);
        float ml0 = -1e30f, ml1 = -1e30f;
#pragma unroll
        for (int nt = 0; nt < 8; nt++) {
            const int c0 = k0 + nt * 8 + lc * 2;
            s[nt][0] *= scale; s[nt][1] *= scale;
            s[nt][2] *= scale; s[nt][3] *= scale;
            if (domask) {
                if (c0     > row0) s[nt][0] = -1e30f;
                if (c0 + 1 > row0) s[nt][1] = -1e30f;
                if (c0     > row1) s[nt][2] = -1e30f;
                if (c0 + 1 > row1) s[nt][3] = -1e30f;
            }
            ml0 = fmaxf(ml0, fmaxf(s[nt][0], s[nt][1]));
            ml1 = fmaxf(ml1, fmaxf(s[nt][2], s[nt][3]));
        }
        ml0 = fmaxf(ml0, __shfl_xor_sync(0xffffffffu, ml0, 1));
        ml0 = fmaxf(ml0, __shfl_xor_sync(0xffffffffu, ml0, 2));
        ml1 = fmaxf(ml1, __shfl_xor_sync(0xffffffffu, ml1, 1));
        ml1 = fmaxf(ml1, __shfl_xor_sync(0xffffffffu, ml1, 2));

        const float mn0 = fmaxf(m0, ml0);
        const float mn1 = fmaxf(m1, ml1);
        const float f0 = __expf(m0 - mn0);
        const float f1 = __expf(m1 - mn1);
        m0 = mn0; m1 = mn1;

        float rs0 = 0.0f, rs1 = 0.0f;
#pragma unroll
        for (int nt = 0; nt < 8; nt++) {
            s[nt][0] = __expf(s[nt][0] - mn0);
            s[nt][1] = __expf(s[nt][1] - mn0);
            s[nt][2] = __expf(s[nt][2] - mn1);
            s[nt][3] = __expf(s[nt][3] - mn1);
            rs0 += s[nt][0] + s[nt][1];
            rs1 += s[nt][2] + s[nt][3];
        }
        rs0 += __shfl_xor_sync(0xffffffffu, rs0, 1);
        rs0 += __shfl_xor_sync(0xffffffffu, rs0, 2);
        rs1 += __shfl_xor_sync(0xffffffffu, rs1, 1);
        rs1 += __shfl_xor_sync(0xffffffffu, rs1, 2);
        l0 = l0 * f0 + rs0;
        l1 = l1 * f1 + rs1;

#pragma unroll
        for (int nt = 0; nt < 16; nt++) {
            o[nt][0] *= f0; o[nt][1] *= f0;
            o[nt][2] *= f1; o[nt][3] *= f1;
        }

#pragma unroll
        for (int nt = 0; nt < 8; nt++) {
            *(uint2*)&Pw[lr * 68 + nt * 8 + lc * 2] =
                make_uint2(f2tf(s[nt][0]), f2tf(s[nt][1]));
            *(uint2*)&Pw[(lr + 8) * 68 + nt * 8 + lc * 2] =
                make_uint2(f2tf(s[nt][2]), f2tf(s[nt][3]));
        }
        __syncwarp();

#pragma unroll
        for (int ks = 0; ks < 8; ks++) {
            uint32_t a[4];
            a[0] = Pw[lr * 68 + ks * 8 + lc];
            a[1] = Pw[(lr + 8) * 68 + ks * 8 + lc];
            a[2] = Pw[lr * 68 + ks * 8 + lc + 4];
            a[3] = Pw[(lr + 8) * 68 + ks * 8 + lc + 4];
#pragma unroll
            for (int nt = 0; nt < 16; nt++) {
                uint32_t bf[2];
                *(uint2*)bf = *(const uint2*)&VB[(nt * 8 + ks) * 66 + lid * 2];
                mma_tf32(o[nt], a, bf);
            }
        }
    }

    const float inv0 = 1.0f / l0;
    const float inv1 = 1.0f / l1;
    float* O0 = g_O + (((size_t)b * SEQ + row0) * NHEADS + h) * DHEAD;
    float* O1 = g_O + (((size_t)b * SEQ + row1) * NHEADS + h) * DHEAD;
#pragma unroll
    for (int nt = 0; nt < 16; nt++) {
        const int col = nt * 8 + lc * 2;
        *(float2*)(O0 + col) = make_float2(o[nt][0] * inv0, o[nt][1] * inv0);
        *(float2*)(O1 + col) = make_float2(o[nt][2] * inv1, o[nt][3] * inv1);
    }
}

// ---------------------------------------------------------------------------
// Launch
// ---------------------------------------------------------------------------
extern "C" void kernel_launch(void* const* d_in, const int* in_sizes, int n_in,
                              void* d_out, int out_size)
{
    const float* x    = (const float*)d_in[0];
    const float* Wqkv = (const float*)d_in[1];
    const float* Wout = (const float*)d_in[2];
    float* out = (float*)d_out;

    cudaFuncSetAttribute(gemm_f<1>, cudaFuncAttributeMaxDynamicSharedMemorySize, GF_SMEM);
    cudaFuncSetAttribute(gemm_f<0>, cudaFuncAttributeMaxDynamicSharedMemorySize, GF_SMEM);
    cudaFuncSetAttribute(flash_attn_mma, cudaFuncAttributeMaxDynamicSharedMemorySize, ATT2_SMEM);

    uint32_t *xf, *of, *wqf, *wof;
    cudaGetSymbolAddress((void**)&xf,  g_xf);
    cudaGetSymbolAddress((void**)&of,  g_of);
    cudaGetSymbolAddress((void**)&wqf, g_wqf);
    cudaGetSymbolAddress((void**)&wof, g_wof);
    float* oPtr = nullptr;
    cudaGetSymbolAddress((void**)&oPtr, g_O);

    // Pre-convert operands into tf32 fragment layouts
    conv_A<<<dim3(NCH, 32), 256>>>(x,    xf);
    conv_B<<<dim3(NCH, 48), 256>>>(Wqkv, wqf);
    conv_B<<<dim3(NCH, 16), 256>>>(Wout, wof);

    // Stage 1: QKV projection (fragment-fed tensor cores, scatter epilogue)
    gemm_f<1><<<dim3(24, 32), 256, GF_SMEM>>>(xf, wqf, nullptr);

    // Stage 2: flash attention (tensor cores)
    flash_attn_mma<<<dim3(SEQ / ABR, BATCH * NHEADS), 256, ATT2_SMEM>>>();

    // Stage 3: convert attention output, then output projection
    conv_A<<<dim3(NCH, 32), 256>>>(oPtr, of);
    gemm_f<0><<<dim3(8, 32), 256, GF_SMEM>>>(of, wof, out);
}

// round 6
// speedup vs baseline: 3.7493x; 1.0370x over previous
#include <cuda_runtime.h>
#include <cstdint>

// Problem constants
#define BATCH   2
#define SEQ     2048
#define DMODEL  2048
#define NHEADS  16
#define DHEAD   128

#define NCH 64                     // K chunks of 32 (K = 2048)

// ---------------------------------------------------------------------------
// Scratch (alloc-free: __device__ globals)
// ---------------------------------------------------------------------------
__device__ float g_Q[(size_t)BATCH * NHEADS * SEQ * DHEAD];
__device__ float g_K[(size_t)BATCH * NHEADS * SEQ * DHEAD];
__device__ float g_V[(size_t)BATCH * NHEADS * SEQ * DHEAD];
__device__ float g_O[(size_t)BATCH * SEQ * DMODEL];

// tf32 pre-converted fragment-layout operands
__device__ __align__(128) uint32_t g_xf [(size_t)32 * NCH * 4096];   // x      [4096,2048]
__device__ __align__(128) uint32_t g_of [(size_t)32 * NCH * 4096];   // g_O    [4096,2048]
__device__ __align__(128) uint32_t g_wqf[(size_t)48 * NCH * 4096];   // W_qkv  [6144,2048]
__device__ __align__(128) uint32_t g_wof[(size_t)16 * NCH * 4096];   // W_out  [2048,2048]

__device__ __forceinline__ uint32_t f2tf(float x) {
    uint32_t r;
    asm("cvt.rna.tf32.f32 %0, %1;" : "=r"(r) : "f"(x));
    return r;
}

__device__ __forceinline__ void mma_tf32(float* d, const uint32_t* a, const uint32_t* b) {
    asm volatile(
        "mma.sync.aligned.m16n8k8.row.col.f32.tf32.tf32.f32 "
        "{%0,%1,%2,%3}, {%4,%5,%6,%7}, {%8,%9}, {%0,%1,%2,%3};"
        : "+f"(d[0]), "+f"(d[1]), "+f"(d[2]), "+f"(d[3])
        : "r"(a[0]), "r"(a[1]), "r"(a[2]), "r"(a[3]), "r"(b[0]), "r"(b[1]));
}

__device__ __forceinline__ void cpa16(uint32_t dst, const void* src) {
    asm volatile("cp.async.cg.shared.global [%0], [%1], 16;"
                 :: "r"(dst), "l"(src) : "memory");
}
#define CPA_COMMIT() asm volatile("cp.async.commit_group;" ::: "memory")
#define CPA_WAIT(n)  asm volatile("cp.async.wait_group %0;" :: "n"(n) : "memory")

__device__ __forceinline__ uint32_t smem_u32(const void* p) {
    uint32_t a;
    asm("{ .reg .u64 t; cvta.to.shared.u64 t, %1; cvt.u32.u64 %0, t; }"
        : "=r"(a) : "l"(p));
    return a;
}

// ---------------------------------------------------------------------------
// Conversion kernels: fp32 row-major -> tf32 fragment layout
// ---------------------------------------------------------------------------
__global__ void __launch_bounds__(256)
conv_A(const float* __restrict__ src, uint32_t* __restrict__ dst)
{
    __shared__ float s[128][33];
    const int ch = blockIdx.x, mb = blockIdx.y, tid = threadIdx.x;
    const float* base = src + (size_t)mb * 128 * DMODEL + ch * 32;
#pragma unroll
    for (int i = 0; i < 4; i++) {
        const int idx = tid + i * 256;
        const int row = idx >> 3, c4 = idx & 7;
        float4 v = *(const float4*)(base + (size_t)row * DMODEL + c4 * 4);
        s[row][c4 * 4 + 0] = v.x; s[row][c4 * 4 + 1] = v.y;
        s[row][c4 * 4 + 2] = v.z; s[row][c4 * 4 + 3] = v.w;
    }
    __syncthreads();
    uint32_t* out = dst + ((size_t)mb * NCH + ch) * 4096;
#pragma unroll
    for (int i = 0; i < 4; i++) {
        const int u = tid + i * 256;
        const int blk = u >> 5, lane = u & 31;
        const int gm = blk >> 2, ks = blk & 3;
        const int r = lane >> 2, kl = lane & 3;
        uint4 w = make_uint4(
            f2tf(s[gm * 16 + r    ][ks * 8 + kl    ]),
            f2tf(s[gm * 16 + r + 8][ks * 8 + kl    ]),
            f2tf(s[gm * 16 + r    ][ks * 8 + kl + 4]),
            f2tf(s[gm * 16 + r + 8][ks * 8 + kl + 4]));
        *(uint4*)(out + (size_t)u * 4) = w;
    }
}

__global__ void __launch_bounds__(256)
conv_B(const float* __restrict__ src, uint32_t* __restrict__ dst)
{
    __shared__ float s[128][33];
    const int ch = blockIdx.x, nb = blockIdx.y, tid = threadIdx.x;
    const float* base = src + (size_t)nb * 128 * DMODEL + ch * 32;
#pragma unroll
    for (int i = 0; i < 4; i++) {
        const int idx = tid + i * 256;
        const int row = idx >> 3, c4 = idx & 7;
        float4 v = *(const float4*)(base + (size_t)row * DMODEL + c4 * 4);
        s[row][c4 * 4 + 0] = v.x; s[row][c4 * 4 + 1] = v.y;
        s[row][c4 * 4 + 2] = v.z; s[row][c4 * 4 + 3] = v.w;
    }
    __syncthreads();
    uint32_t* out = dst + ((size_t)nb * NCH + ch) * 4096;
#pragma unroll
    for (int i = 0; i < 8; i++) {
        const int u = tid + i * 256;
        const int blk = u >> 5, lane = u & 31;
        const int gn = blk >> 2, ks = blk & 3;
        const int n8 = lane >> 2, kl = lane & 3;
        uint2 w = make_uint2(
            f2tf(s[gn * 8 + n8][ks * 8 + kl    ]),
            f2tf(s[gn * 8 + n8][ks * 8 + kl + 4]));
        *(uint2*)(out + (size_t)u * 2) = w;
    }
}

// ---------------------------------------------------------------------------
// Fragment-fed tf32 GEMM: C[m,n] = sum_k A[m,k]*B[n,k], K = 2048.
// CTA 128(m) x 256(n), 256 threads, 8 warps (2m x 4n), warp tile 64x64.
// 4-stage cp.async ring, prefetch distance 2, ONE barrier per chunk.
// Stage skew safety: fastest warp (one iter ahead) writes stage (c+3)&3
// while laggards read stage c&3 — disjoint; barrier bounds skew to 1 iter.
// MODE 0: C row-major [M, 2048].  MODE 1: scatter QKV (fp32).
// ---------------------------------------------------------------------------
#define STAGE_U32 12288
#define GF_SMEM   (4 * STAGE_U32 * 4)    // 196608 bytes

template <int MODE>
__global__ void __launch_bounds__(256)
gemm_f(const uint32_t* __restrict__ Af, const uint32_t* __restrict__ Bf,
       float* __restrict__ C)
{
    extern __shared__ uint32_t us[];
    const int tid = threadIdx.x;
    const int wid = tid >> 5;
    const int lid = tid & 31;
    const int wm  = wid & 1;
    const int wn  = wid >> 1;
    const int mb  = blockIdx.y;
    const int nbx = blockIdx.x;
    const uint32_t sb = smem_u32(us);

    float acc[4][8][4];
#pragma unroll
    for (int i = 0; i < 4; i++)
#pragma unroll
        for (int j = 0; j < 8; j++)
#pragma unroll
            for (int v = 0; v < 4; v++) acc[i][j][v] = 0.0f;

    auto issue = [&](int c, int st) {
        const uint32_t sA = sb + st * (STAGE_U32 * 4);
        const uint32_t sB = sA + 16384;
        const uint32_t* gA  = Af + ((size_t)mb * NCH + c) * 4096;
        const uint32_t* gB0 = Bf + ((size_t)(2 * nbx)     * NCH + c) * 4096;
        const uint32_t* gB1 = Bf + ((size_t)(2 * nbx + 1) * NCH + c) * 4096;
#pragma unroll
        for (int i = 0; i < 4; i++) {
            const int o = tid + i * 256;
            cpa16(sA + o * 16, gA + (size_t)o * 4);
        }
#pragma unroll
        for (int i = 0; i < 4; i++) {
            const int o = tid + i * 256;
            cpa16(sB + o * 16, gB0 + (size_t)o * 4);
        }
#pragma unroll
        for (int i = 0; i < 4; i++) {
            const int o = tid + i * 256;
            cpa16(sB + 16384 + o * 16, gB1 + (size_t)o * 4);
        }
        CPA_COMMIT();
    };

    issue(0, 0);
    issue(1, 1);

    for (int c = 0; c < NCH; ++c) {
        const int st = c & 3;
        if (c + 2 < NCH)      { issue(c + 2, (c + 2) & 3); CPA_WAIT(2); }
        else if (c + 1 < NCH) { CPA_WAIT(1); }
        else                  { CPA_WAIT(0); }
        __syncthreads();

        const uint32_t* uA = us + st * STAGE_U32;
        const uint32_t* uB = uA + 4096;
#pragma unroll
        for (int ks = 0; ks < 4; ks++) {
            uint32_t a[4][4], b[8][2];
#pragma unroll
            for (int mt = 0; mt < 4; mt++)
                *(uint4*)a[mt] = *(const uint4*)&uA[(((wm * 4 + mt) * 4 + ks) * 32 + lid) * 4];
#pragma unroll
            for (int nt = 0; nt < 8; nt++) {
                const int gn = wn * 8 + nt;
                *(uint2*)b[nt] = *(const uint2*)
                    &uB[((gn >> 4) * 4096) + (((gn & 15) * 4 + ks) * 32 + lid) * 2];
            }
#pragma unroll
            for (int mt = 0; mt < 4; mt++)
#pragma unroll
                for (int nt = 0; nt < 8; nt++)
                    mma_tf32(acc[mt][nt], a[mt], b[nt]);
        }
    }

    // ---- epilogue ----
    const int lr  = lid >> 2;
    const int lc2 = (lid & 3) * 2;
    const int m0  = mb * 128;
    const int n0  = nbx * 256;
#pragma unroll
    for (int mt = 0; mt < 4; mt++) {
        const int m = m0 + wm * 64 + mt * 16 + lr;
#pragma unroll
        for (int nt = 0; nt < 8; nt++) {
            const int cg = n0 + wn * 64 + nt * 8 + lc2;
            if (MODE == 0) {
                float* dst = C + (size_t)m * DMODEL + cg;
                *(float2*)dst                         = make_float2(acc[mt][nt][0], acc[mt][nt][1]);
                *(float2*)(dst + (size_t)8 * DMODEL)  = make_float2(acc[mt][nt][2], acc[mt][nt][3]);
            } else {
                const int t = cg >> 11;
                const int h = (cg >> 7) & (NHEADS - 1);
                const int d = cg & (DHEAD - 1);
                const int b = m >> 11;
                const int s = m & (SEQ - 1);
                float* basep = (t == 0 ? g_Q : (t == 1 ? g_K : g_V));
                float* dst = basep + ((size_t)(b * NHEADS + h) * SEQ + s) * DHEAD + d;
                *(float2*)dst                = make_float2(acc[mt][nt][0], acc[mt][nt][1]);
                *(float2*)(dst + 8 * DHEAD)  = make_float2(acc[mt][nt][2], acc[mt][nt][3]);
            }
        }
    }
}

// ---------------------------------------------------------------------------
// Flash attention on tensor cores (tf32 mma.sync), causal. (unchanged)
// ---------------------------------------------------------------------------
#define ABR 128
#define ABC 64

#define AQ_OFF   0
#define AQ_BYTES (128 * 132 * 4)
#define AK_OFF   (AQ_OFF + AQ_BYTES)
#define AK_BYTES (128 * 66 * 4)
#define AV_OFF   (AK_OFF + AK_BYTES)
#define AV_BYTES (128 * 66 * 4)
#define AP_OFF   (AV_OFF + AV_BYTES)
#define AP_BYTES (8 * 16 * 68 * 4)
#define ATT2_SMEM (AP_OFF + AP_BYTES)

__global__ void __launch_bounds__(256, 1)
flash_attn_mma()
{
    extern __shared__ char sm[];
    uint32_t* QA = (uint32_t*)(sm + AQ_OFF);
    uint32_t* KB = (uint32_t*)(sm + AK_OFF);
    uint32_t* VB = (uint32_t*)(sm + AV_OFF);

    const int tid = threadIdx.x;
    const int wid = tid >> 5;
    const int lid = tid & 31;
    const int qb  = gridDim.x - 1 - blockIdx.x;
    const int bh  = blockIdx.y;
    const int q0  = qb * ABR;
    const int b   = bh >> 4;
    const int h   = bh & (NHEADS - 1);

    const float* Qg = g_Q + (size_t)bh * SEQ * DHEAD;
    const float* Kg = g_K + (size_t)bh * SEQ * DHEAD;
    const float* Vg = g_V + (size_t)bh * SEQ * DHEAD;

#pragma unroll
    for (int it = 0; it < 16; it++) {
        const int idx = tid + it * 256;
        const int d4  = idx >> 7;
        const int r   = idx & 127;
        float4 v = *(const float4*)(Qg + (size_t)(q0 + r) * DHEAD + d4 * 4);
        const int w    = r >> 4;
        const int kt   = d4 >> 1;
        const int slot = ((d4 & 1) ? 2 : 0) + ((r >> 3) & 1);
        uint32_t* p = &QA[(kt * 8 + w) * 132 + ((r & 7) * 4) * 4 + slot];
        p[0]  = f2tf(v.x);
        p[4]  = f2tf(v.y);
        p[8]  = f2tf(v.z);
        p[12] = f2tf(v.w);
    }

    const int lr = lid >> 2;
    const int lc = lid & 3;
    uint32_t* Pw = (uint32_t*)(sm + AP_OFF) + wid * (16 * 68);

    float o[16][4];
#pragma unroll
    for (int nt = 0; nt < 16; nt++)
#pragma unroll
        for (int v = 0; v < 4; v++) o[nt][v] = 0.0f;

    float m0 = -1e30f, m1 = -1e30f, l0 = 0.0f, l1 = 0.0f;
    const float scale = 0.08838834764831845f;
    const int row0 = q0 + wid * 16 + lr;
    const int row1 = row0 + 8;

    const int nkb = 2 * qb + 2;
    for (int kb = 0; kb < nkb; kb++) {
        const int k0 = kb * ABC;
        __syncthreads();

#pragma unroll
        for (int it = 0; it < 8; it++) {
            const int idx = tid + it * 256;
            const int d4  = idx >> 6;
            const int s   = idx & 63;
            float4 kv = *(const float4*)(Kg + (size_t)(k0 + s) * DHEAD + d4 * 4);
            {
                const int blockid = (d4 >> 1) * 8 + (s >> 3);
                const int slot = (d4 & 1);
                uint32_t* p = &KB[blockid * 66 + ((s & 7) * 4) * 2 + slot];
                p[0] = f2tf(kv.x);
                p[2] = f2tf(kv.y);
                p[4] = f2tf(kv.z);
                p[6] = f2tf(kv.w);
            }
            float4 vv = *(const float4*)(Vg + (size_t)(k0 + s) * DHEAD + d4 * 4);
            {
                const int blockid = (d4 >> 1) * 8 + (s >> 3);
                const int slot = ((s & 7) < 4) ? 0 : 1;
                const int lane0 = (d4 & 1) * 16 + (s & 3);
                uint32_t* p = &VB[blockid * 66 + lane0 * 2 + slot];
                p[0]  = f2tf(vv.x);
                p[8]  = f2tf(vv.y);
                p[16] = f2tf(vv.z);
                p[24] = f2tf(vv.w);
            }
        }
        __syncthreads();

        float s[8][4];
#pragma unroll
        for (int nt = 0; nt < 8; nt++)
#pragma unroll
            for (int v = 0; v < 4; v++) s[nt][v] = 0.0f;

#pragma unroll
        for (int kt = 0; kt < 16; kt++) {
            uint32_t a[4];
            *(uint4*)a = *(const uint4*)&QA[(kt * 8 + wid) * 132 + lid * 4];
#pragma unroll
            for (int nt = 0; nt < 8; nt++) {
                uint32_t bf[2];
                *(uint2*)bf = *(const uint2*)&KB[(kt * 8 + nt) * 66 + lid * 2];
                mma_tf32(s[nt], a, bf);
            }
        }

        const bool domask = (kb >= 2 * qb);
        float ml0 = -1e30f, ml1 = -1e30f;
#pragma unroll
        for (int nt = 0; nt < 8; nt++) {
            const int c0 = k0 + nt * 8 + lc * 2;
            s[nt][0] *= scale; s[nt][1] *= scale;
            s[nt][2] *= scale; s[nt][3] *= scale;
            if (domask) {
                if (c0     > row0) s[nt][0] = -1e30f;
                if (c0 + 1 > row0) s[nt][1] = -1e30f;
                if (c0     > row1) s[nt][2] = -1e30f;
                if (c0 + 1 > row1) s[nt][3] = -1e30f;
            }
            ml0 = fmaxf(ml0, fmaxf(s[nt][0], s[nt][1]));
            ml1 = fmaxf(ml1, fmaxf(s[nt][2], s[nt][3]));
        }
        ml0 = fmaxf(ml0, __shfl_xor_sync(0xffffffffu, ml0, 1));
        ml0 = fmaxf(ml0, __shfl_xor_sync(0xffffffffu, ml0, 2));
        ml1 = fmaxf(ml1, __shfl_xor_sync(0xffffffffu, ml1, 1));
        ml1 = fmaxf(ml1, __shfl_xor_sync(0xffffffffu, ml1, 2));

        const float mn0 = fmaxf(m0, ml0);
        const float mn1 = fmaxf(m1, ml1);
        const float f0 = __expf(m0 - mn0);
        const float f1 = __expf(m1 - mn1);
        m0 = mn0; m1 = mn1;

        float rs0 = 0.0f, rs1 = 0.0f;
#pragma unroll
        for (int nt = 0; nt < 8; nt++) {
            s[nt][0] = __expf(s[nt][0] - mn0);
            s[nt][1] = __expf(s[nt][1] - mn0);
            s[nt][2] = __expf(s[nt][2] - mn1);
            s[nt][3] = __expf(s[nt][3] - mn1);
            rs0 += s[nt][0] + s[nt][1];
            rs1 += s[nt][2] + s[nt][3];
        }
        rs0 += __shfl_xor_sync(0xffffffffu, rs0, 1);
        rs0 += __shfl_xor_sync(0xffffffffu, rs0, 2);
        rs1 += __shfl_xor_sync(0xffffffffu, rs1, 1);
        rs1 += __shfl_xor_sync(0xffffffffu, rs1, 2);
        l0 = l0 * f0 + rs0;
        l1 = l1 * f1 + rs1;

#pragma unroll
        for (int nt = 0; nt < 16; nt++) {
            o[nt][0] *= f0; o[nt][1] *= f0;
            o[nt][2] *= f1; o[nt][3] *= f1;
        }

#pragma unroll
        for (int nt = 0; nt < 8; nt++) {
            *(uint2*)&Pw[lr * 68 + nt * 8 + lc * 2] =
                make_uint2(f2tf(s[nt][0]), f2tf(s[nt][1]));
            *(uint2*)&Pw[(lr + 8) * 68 + nt * 8 + lc * 2] =
                make_uint2(f2tf(s[nt][2]), f2tf(s[nt][3]));
        }
        __syncwarp();

#pragma unroll
        for (int ks = 0; ks < 8; ks++) {
            uint32_t a[4];
            a[0] = Pw[lr * 68 + ks * 8 + lc];
            a[1] = Pw[(lr + 8) * 68 + ks * 8 + lc];
            a[2] = Pw[lr * 68 + ks * 8 + lc + 4];
            a[3] = Pw[(lr + 8) * 68 + ks * 8 + lc + 4];
#pragma unroll
            for (int nt = 0; nt < 16; nt++) {
                uint32_t bf[2];
                *(uint2*)bf = *(const uint2*)&VB[(nt * 8 + ks) * 66 + lid * 2];
                mma_tf32(o[nt], a, bf);
            }
        }
    }

    const float inv0 = 1.0f / l0;
    const float inv1 = 1.0f / l1;
    float* O0 = g_O + (((size_t)b * SEQ + row0) * NHEADS + h) * DHEAD;
    float* O1 = g_O + (((size_t)b * SEQ + row1) * NHEADS + h) * DHEAD;
#pragma unroll
    for (int nt = 0; nt < 16; nt++) {
        const int col = nt * 8 + lc * 2;
        *(float2*)(O0 + col) = make_float2(o[nt][0] * inv0, o[nt][1] * inv0);
        *(float2*)(O1 + col) = make_float2(o[nt][2] * inv1, o[nt][3] * inv1);
    }
}

// ---------------------------------------------------------------------------
// Launch
// ---------------------------------------------------------------------------
extern "C" void kernel_launch(void* const* d_in, const int* in_sizes, int n_in,
                              void* d_out, int out_size)
{
    const float* x    = (const float*)d_in[0];
    const float* Wqkv = (const float*)d_in[1];
    const float* Wout = (const float*)d_in[2];
    float* out = (float*)d_out;

    cudaFuncSetAttribute(gemm_f<1>, cudaFuncAttributeMaxDynamicSharedMemorySize, GF_SMEM);
    cudaFuncSetAttribute(gemm_f<0>, cudaFuncAttributeMaxDynamicSharedMemorySize, GF_SMEM);
    cudaFuncSetAttribute(flash_attn_mma, cudaFuncAttributeMaxDynamicSharedMemorySize, ATT2_SMEM);

    uint32_t *xf, *of, *wqf, *wof;
    cudaGetSymbolAddress((void**)&xf,  g_xf);
    cudaGetSymbolAddress((void**)&of,  g_of);
    cudaGetSymbolAddress((void**)&wqf, g_wqf);
    cudaGetSymbolAddress((void**)&wof, g_wof);
    float* oPtr = nullptr;
    cudaGetSymbolAddress((void**)&oPtr, g_O);

    // Pre-convert operands into tf32 fragment layouts
    conv_A<<<dim3(NCH, 32), 256>>>(x,    xf);
    conv_B<<<dim3(NCH, 48), 256>>>(Wqkv, wqf);
    conv_B<<<dim3(NCH, 16), 256>>>(Wout, wof);

    // Stage 1: QKV projection (fragment-fed tensor cores, scatter epilogue)
    gemm_f<1><<<dim3(24, 32), 256, GF_SMEM>>>(xf, wqf, nullptr);

    // Stage 2: flash attention (tensor cores)
    flash_attn_mma<<<dim3(SEQ / ABR, BATCH * NHEADS), 256, ATT2_SMEM>>>();

    // Stage 3: convert attention output, then output projection
    conv_A<<<dim3(NCH, 32), 256>>>(oPtr, of);
    gemm_f<0><<<dim3(8, 32), 256, GF_SMEM>>>(of, wof, out);
}